// round 4
// baseline (speedup 1.0000x reference)
#include <cuda_runtime.h>
#include <cuda_bf16.h>

// BERTEmbedding: out[b,l,:] = token_table[seq[b,l],:]
//                           + mean_{g<cnt}(genre_table[gids[seq[b,l],g],:])
//                           + pos_table[l,:]
//
// B=256, L=200, EMBED=128 (32 float4), MAX_G=8.
//
// R4: single-wave persistent grid. 1184 CTAs (148 SM x 8 CTAs of 8 warps
// = 64 warps/SM, exactly one wave). Each warp grid-strides over ~5.4 tokens,
// prefetching the next iteration's seq index to hide the dependent-gather
// chain. Lane k owns float4 at dim 4k (perfectly coalesced 512B/warp).

#define NUM_TOKENS (256 * 200)
#define SEQ_L 200
#define MAX_G 8
#define GRID_BLOCKS 1184
#define BLOCK_THREADS 256
#define TOTAL_WARPS (GRID_BLOCKS * (BLOCK_THREADS / 32))   // 9472

__global__ __launch_bounds__(BLOCK_THREADS) void bert_embed_kernel(
    const int* __restrict__ seq,          // [256*200]
    const float4* __restrict__ tok_tab,   // [VOCAB,32]
    const float4* __restrict__ gen_tab,   // [21,32]
    const float4* __restrict__ pos_tab,   // [200,32]
    const int4* __restrict__ tgid,        // [VOCAB,8] as [VOCAB,2] int4
    const int* __restrict__ gcnt,         // [VOCAB]
    float4* __restrict__ out)             // [256*200,32]
{
    const int lane = threadIdx.x & 31;
    const int w0   = (blockIdx.x * BLOCK_THREADS + threadIdx.x) >> 5;

    // Prefetch the first token id for this warp.
    int i = w0;
    int t_next = (i < NUM_TOKENS) ? __ldg(&seq[i]) : 0;

    for (; i < NUM_TOKENS; i += TOTAL_WARPS) {
        const int t = t_next;

        // Prefetch next iteration's seq (overlaps with everything below).
        const int inext = i + TOTAL_WARPS;
        if (inext < NUM_TOKENS) t_next = __ldg(&seq[inext]);

        // All level-2 loads independent — issued back-to-back for MLP.
        const int    cnt = __ldg(&gcnt[t]);          // warp-uniform
        const int4   ga  = __ldg(&tgid[t * 2]);      // warp-uniform
        const int4   gb  = __ldg(&tgid[t * 2 + 1]);  // warp-uniform
        const float4 tok = __ldg(&tok_tab[t * 32 + lane]);
        const int    l   = i % SEQ_L;
        const float4 pos = __ldg(&pos_tab[l * 32 + lane]);

        const int gid[MAX_G] = {ga.x, ga.y, ga.z, ga.w, gb.x, gb.y, gb.z, gb.w};

        float4 s = make_float4(0.f, 0.f, 0.f, 0.f);
        #pragma unroll
        for (int g = 0; g < MAX_G; g++) {
            if (g < cnt) {                            // warp-uniform branch
                const float4 ge = __ldg(&gen_tab[gid[g] * 32 + lane]); // L1-hot
                s.x += ge.x; s.y += ge.y; s.z += ge.z; s.w += ge.w;
            }
        }

        const float inv = 1.0f / (float)cnt;
        float4 o;
        o.x = tok.x + pos.x + s.x * inv;
        o.y = tok.y + pos.y + s.y * inv;
        o.z = tok.z + pos.z + s.z * inv;
        o.w = tok.w + pos.w + s.w * inv;

        out[i * 32 + lane] = o;
    }
}

extern "C" void kernel_launch(void* const* d_in, const int* in_sizes, int n_in,
                              void* d_out, int out_size) {
    const int*    seq     = (const int*)d_in[0];
    const float4* tok_tab = (const float4*)d_in[1];
    const float4* gen_tab = (const float4*)d_in[2];
    const float4* pos_tab = (const float4*)d_in[3];
    const int4*   tgid    = (const int4*)d_in[4];
    const int*    gcnt    = (const int*)d_in[5];
    float4*       out     = (float4*)d_out;

    bert_embed_kernel<<<GRID_BLOCKS, BLOCK_THREADS>>>(
        seq, tok_tab, gen_tab, pos_tab, tgid, gcnt, out);
}

// round 5
// speedup vs baseline: 1.1359x; 1.1359x over previous
#include <cuda_runtime.h>

// BERTEmbedding: out[b,l,:] = token_table[seq[b,l],:]
//                           + mean_{g<cnt}(genre_table[gids[seq[b,l],g],:])
//                           + pos_table[l,:]
//
// R5: cut issue-slot cost with Blackwell packed f32x2 math (add/fma.rn.f32x2,
// only reachable via inline PTX). All 16B vectors loaded as ulonglong2 so each
// 64-bit register is directly a packed f32x2 operand. Warp per token
// (R1 layout — best measured occupancy), lane k owns dims [4k,4k+4).

#define NUM_TOKENS (256 * 200)
#define SEQ_L 200
#define MAX_G 8

typedef unsigned long long u64;

__device__ __forceinline__ u64 addx2(u64 a, u64 b) {
    u64 r; asm("add.rn.f32x2 %0, %1, %2;" : "=l"(r) : "l"(a), "l"(b)); return r;
}
__device__ __forceinline__ u64 fmax2(u64 a, u64 b, u64 c) {
    u64 r; asm("fma.rn.f32x2 %0, %1, %2, %3;" : "=l"(r) : "l"(a), "l"(b), "l"(c)); return r;
}
__device__ __forceinline__ u64 pack2(float lo, float hi) {
    u64 r; asm("mov.b64 %0, {%1, %2};" : "=l"(r) : "f"(lo), "f"(hi)); return r;
}

__global__ __launch_bounds__(256) void bert_embed_kernel(
    const int* __restrict__ seq,              // [256*200]
    const ulonglong2* __restrict__ tok_tab,   // [VOCAB,32] float4 rows
    const ulonglong2* __restrict__ gen_tab,   // [21,32]
    const ulonglong2* __restrict__ pos_tab,   // [200,32]
    const int4* __restrict__ tgid,            // [VOCAB,8] as [VOCAB,2] int4
    const int* __restrict__ gcnt,             // [VOCAB]
    ulonglong2* __restrict__ out)             // [256*200,32]
{
    const int warp = (blockIdx.x * blockDim.x + threadIdx.x) >> 5;
    const int lane = threadIdx.x & 31;

    const int l = warp % SEQ_L;
    const int t = __ldg(&seq[warp]);               // warp-uniform

    // Independent level-2 loads, issued back-to-back.
    const int        cnt = __ldg(&gcnt[t]);        // warp-uniform
    const int4       ga  = __ldg(&tgid[t * 2]);    // warp-uniform
    const int4       gb  = __ldg(&tgid[t * 2 + 1]);
    const ulonglong2 tok = __ldg(&tok_tab[t * 32 + lane]);
    const ulonglong2 pos = __ldg(&pos_tab[l * 32 + lane]);

    const int gid[MAX_G] = {ga.x, ga.y, ga.z, ga.w, gb.x, gb.y, gb.z, gb.w};

    u64 s01 = 0, s23 = 0;   // 0x0 == packed {0.f, 0.f}
    #pragma unroll
    for (int g = 0; g < MAX_G; g++) {
        if (g < cnt) {                              // warp-uniform predicate
            const ulonglong2 ge = __ldg(&gen_tab[gid[g] * 32 + lane]); // L1-hot
            s01 = addx2(s01, ge.x);
            s23 = addx2(s23, ge.y);
        }
    }

    const float invf = 1.0f / (float)cnt;
    const u64 inv2 = pack2(invf, invf);

    ulonglong2 o;
    o.x = fmax2(s01, inv2, addx2(tok.x, pos.x));
    o.y = fmax2(s23, inv2, addx2(tok.y, pos.y));

    out[warp * 32 + lane] = o;
}

extern "C" void kernel_launch(void* const* d_in, const int* in_sizes, int n_in,
                              void* d_out, int out_size) {
    const int*        seq     = (const int*)d_in[0];
    const ulonglong2* tok_tab = (const ulonglong2*)d_in[1];
    const ulonglong2* gen_tab = (const ulonglong2*)d_in[2];
    const ulonglong2* pos_tab = (const ulonglong2*)d_in[3];
    const int4*       tgid    = (const int4*)d_in[4];
    const int*        gcnt    = (const int*)d_in[5];
    ulonglong2*       out     = (ulonglong2*)d_out;

    // one warp per token, 8 warps per block -> 6400 blocks, no remainder
    bert_embed_kernel<<<NUM_TOKENS / 8, 256>>>(
        seq, tok_tab, gen_tab, pos_tab, tgid, gcnt, out);
}